// round 1
// baseline (speedup 1.0000x reference)
#include <cuda_runtime.h>
#include <cstdint>

// CustomConv: 3x3 conv, stride 1, pad 1, NHWC x HWIO -> NHWC, + bias + ReLU.
// N=32, H=W=56, Cin=128, Cout=256, all fp32.
//
// Implicit GEMM: M = 32*56*56 = 100352 output pixels, N = 256 couts,
// K = 9*128 = 1152 (ordering (kh,kw,cin) == HWIO weight memory order, so
// B tile loads are plain contiguous rows of the weight tensor).
//
// Tiling: 128(M) x 128(N) per block, BK=8, 256 threads, 8x8 per-thread tile.
// FP32 math via packed fma.rn.f32x2 (Blackwell): accumulators are u64 pairs
// over adjacent output-channel columns -> 2 FMA per issued instruction.

#define H_ 56
#define W_ 56
#define CIN 128
#define COUT 256
#define HW (H_ * W_)            // 3136
#define KTOT 1152               // 9 * 128
#define NCHUNK 144              // KTOT / 8

static __device__ __forceinline__ unsigned long long pk2(float lo, float hi) {
    unsigned long long r;
    asm("mov.b64 %0, {%1, %2};" : "=l"(r) : "f"(lo), "f"(hi));
    return r;
}
static __device__ __forceinline__ void fma2(unsigned long long& d,
                                            unsigned long long a,
                                            unsigned long long b) {
    asm("fma.rn.f32x2 %0, %1, %2, %0;" : "+l"(d) : "l"(a), "l"(b));
}
static __device__ __forceinline__ float lo32(unsigned long long v) {
    return __uint_as_float((unsigned)(v & 0xffffffffu));
}
static __device__ __forceinline__ float hi32(unsigned long long v) {
    return __uint_as_float((unsigned)(v >> 32));
}

__global__ __launch_bounds__(256, 2)
void conv3x3_f32x2_kernel(const float* __restrict__ in,    // [32,56,56,128]
                          const float* __restrict__ wgt,   // [3,3,128,256] = [1152,256]
                          const float* __restrict__ bias,  // [256]
                          float* __restrict__ out)         // [100352,256]
{
    __shared__ float As[8][128];   // [k_local][pixel]
    __shared__ float Bs[8][128];   // [k_local][cout]

    const int tid = threadIdx.x;
    const int coutBase = blockIdx.x * 128;   // 0 or 128
    const int pixBase  = blockIdx.y * 128;   // 0..783*128

    // ---- A-load mapping: thread owns one pixel (tid>>1) and 4 cin (tid&1)*4 ----
    const int pA  = pixBase + (tid >> 1);
    const int n   = pA / HW;
    const int rem = pA - n * HW;
    const int oh  = rem / W_;
    const int ow  = rem - oh * W_;
    const int cinOff = (tid & 1) * 4;
    const int pixLocal = tid >> 1;

    // ---- B-load mapping: 8 rows x 128 cols, one float4 per thread ----
    const int bRow = tid >> 5;         // 0..7
    const int bCol = (tid & 31) * 4;   // 0..124

    const int ty = tid >> 4;   // 0..15 -> pixel sub-tile
    const int tx = tid & 15;   // 0..15 -> cout sub-tile

    unsigned long long acc[8][4];
    #pragma unroll
    for (int i = 0; i < 8; ++i)
        #pragma unroll
        for (int j = 0; j < 4; ++j) acc[i][j] = 0ULL;

    for (int kc = 0; kc < NCHUNK; ++kc) {
        // K-chunk kc covers k = kc*8 .. kc*8+7; 8 | 128 so (kh,kw) fixed per chunk.
        const int f = kc >> 4;                 // kh*3+kw, 0..8
        const int cinBase = (kc & 15) * 8;     // 0..120
        const int kh = f / 3;
        const int kw = f - kh * 3;
        const int ih = oh + kh - 1;
        const int iw = ow + kw - 1;

        float4 av = make_float4(0.f, 0.f, 0.f, 0.f);
        if ((unsigned)ih < (unsigned)H_ && (unsigned)iw < (unsigned)W_) {
            av = *(const float4*)&in[(((n * H_ + ih) * W_ + iw) << 7) + cinBase + cinOff];
        }
        const float4 bv = *(const float4*)&wgt[(kc * 8 + bRow) * COUT + coutBase + bCol];

        __syncthreads();   // previous iteration's smem reads complete
        As[cinOff + 0][pixLocal] = av.x;
        As[cinOff + 1][pixLocal] = av.y;
        As[cinOff + 2][pixLocal] = av.z;
        As[cinOff + 3][pixLocal] = av.w;
        *(float4*)&Bs[bRow][bCol] = bv;
        __syncthreads();

        #pragma unroll
        for (int k = 0; k < 8; ++k) {
            const float4 a0 = *(const float4*)&As[k][ty * 8];
            const float4 a1 = *(const float4*)&As[k][ty * 8 + 4];
            const ulonglong2 bb0 = *(const ulonglong2*)&Bs[k][tx * 8];
            const ulonglong2 bb1 = *(const ulonglong2*)&Bs[k][tx * 8 + 4];
            unsigned long long b2[4];
            b2[0] = bb0.x; b2[1] = bb0.y; b2[2] = bb1.x; b2[3] = bb1.y;
            float a[8];
            a[0] = a0.x; a[1] = a0.y; a[2] = a0.z; a[3] = a0.w;
            a[4] = a1.x; a[5] = a1.y; a[6] = a1.z; a[7] = a1.w;
            #pragma unroll
            for (int i = 0; i < 8; ++i) {
                const unsigned long long a2 = pk2(a[i], a[i]);
                #pragma unroll
                for (int j = 0; j < 4; ++j) fma2(acc[i][j], a2, b2[j]);
            }
        }
    }

    // ---- Epilogue: bias + ReLU, direct stores (output is GEMM-C row-major) ----
    float bv[8];
    *(float4*)&bv[0] = *(const float4*)&bias[coutBase + tx * 8];
    *(float4*)&bv[4] = *(const float4*)&bias[coutBase + tx * 8 + 4];

    #pragma unroll
    for (int i = 0; i < 8; ++i) {
        const int row = pixBase + ty * 8 + i;
        float* orow = out + (size_t)row * COUT + coutBase + tx * 8;
        float r[8];
        #pragma unroll
        for (int j = 0; j < 4; ++j) {
            r[2 * j]     = lo32(acc[i][j]) + bv[2 * j];
            r[2 * j + 1] = hi32(acc[i][j]) + bv[2 * j + 1];
        }
        #pragma unroll
        for (int j = 0; j < 8; ++j) r[j] = r[j] > 0.f ? r[j] : 0.f;
        *(float4*)&orow[0] = make_float4(r[0], r[1], r[2], r[3]);
        *(float4*)&orow[4] = make_float4(r[4], r[5], r[6], r[7]);
    }
}

extern "C" void kernel_launch(void* const* d_in, const int* in_sizes, int n_in,
                              void* d_out, int out_size) {
    const float* prev_a   = (const float*)d_in[0];   // 32*56*56*128
    const float* filter_w = (const float*)d_in[1];   // 3*3*128*256
    const float* filter_b = (const float*)d_in[2];   // 256
    float* out = (float*)d_out;                      // 32*56*56*256

    dim3 grid(COUT / 128, (32 * HW) / 128);  // (2, 784)
    conv3x3_f32x2_kernel<<<grid, 256>>>(prev_a, filter_w, filter_b, out);
}

// round 3
// speedup vs baseline: 3.3940x; 3.3940x over previous
#include <cuda_runtime.h>
#include <cstdint>
#include <cstddef>

// CustomConv 3x3 s1 p1: NHWC(32,56,56,128) x HWIO(3,3,128,256) + bias + ReLU.
// Implicit GEMM, legacy tensor-core path (mma.sync m16n8k8 tf32, sm_80+ PTX --
// tcgen05 is unavailable because the harness compiles PTX for compute_100).
//
// M = 100352 pixels, N = 256, K = 1152 (9 taps x 128 cin).
// CTA tile 128x128, BK = 32 (36 slabs), 8 warps in 4(M)x2(N) grid,
// warp tile 32x64 = 2x8 m16n8k8 tiles, 64 fp32 accs/thread.
// cp.async double-buffered smem; A zero-pads halo via src-size=0.
// Smem swizzle: 16B unit u = (k>>2) ^ (row&7)  -> conflict-free LDS.32 frags.

#define H_ 56
#define W_ 56
#define HW 3136
#define COUT 256
#define NSLAB 36

// Prepacked B: per (cout-tile, slab) the exact 16KB smem image:
// float idx = n*32 + (((k>>2) ^ (n&7))<<2) + (k&3), tf32-rna-rounded.
__device__ float g_Bp[2][NSLAB][4096];

static __device__ __forceinline__ uint32_t smem_u32(const void* p) {
    uint32_t a;
    asm("{ .reg .u64 t; cvta.to.shared.u64 t, %1; cvt.u32.u64 %0, t; }"
        : "=r"(a) : "l"(p));
    return a;
}
static __device__ __forceinline__ float rna_tf32(float x) {
    uint32_t r;
    asm("cvt.rna.tf32.f32 %0, %1;" : "=r"(r) : "f"(x));
    return __uint_as_float(r);
}
static __device__ __forceinline__ void cpasync16(uint32_t dst, const void* src, int sz) {
    asm volatile("cp.async.cg.shared.global [%0], [%1], 16, %2;"
                 :: "r"(dst), "l"(src), "r"(sz) : "memory");
}

#define MMA_TF32(d, a, b)                                                          \
    asm volatile(                                                                  \
        "mma.sync.aligned.m16n8k8.row.col.f32.tf32.tf32.f32 "                      \
        "{%0,%1,%2,%3}, {%4,%5,%6,%7}, {%8,%9}, {%0,%1,%2,%3};"                    \
        : "+f"((d)[0]), "+f"((d)[1]), "+f"((d)[2]), "+f"((d)[3])                   \
        : "r"((a)[0]), "r"((a)[1]), "r"((a)[2]), "r"((a)[3]),                      \
          "r"((b)[0]), "r"((b)[1]))

// ---------------- weight prepack (runs once per launch, ~1.2MB) ----------------
__global__ void prepack_kernel(const float* __restrict__ wgt) {
    const int s  = blockIdx.x;     // 0..35
    const int nt = blockIdx.y;     // 0..1
    const int t  = threadIdx.x;    // 0..255
    const int f  = s >> 2;         // tap 0..8
    const int cs = s & 3;          // cin slab
    float* dst = &g_Bp[nt][s][0];
    #pragma unroll
    for (int e = 0; e < 16; ++e) {
        const int lin = t * 16 + e;
        const int n = lin >> 5;        // cout 0..127
        const int k = lin & 31;        // k within slab
        const int u = (k >> 2) ^ (n & 7);
        dst[n * 32 + u * 4 + (k & 3)] =
            rna_tf32(wgt[(size_t)(f * 128 + cs * 32 + k) * COUT + nt * 128 + n]);
    }
}

// ---------------- main kernel ----------------
// dyn smem: 2 buffers x (A 16KB + B 16KB) = 65536 bytes.
#define SMEM_BYTES 65536

__global__ __launch_bounds__(256, 2)
void conv_mma_tf32(const float* __restrict__ in, const float* __restrict__ bias,
                   float* __restrict__ out) {
    extern __shared__ char smem[];
    const uint32_t sb = smem_u32(smem);
    const int tid  = threadIdx.x;
    const int lane = tid & 31;
    const int wid  = tid >> 5;
    const int g    = lane >> 2;      // groupID 0..7
    const int tig  = lane & 3;       // thread-in-group
    const int wm   = wid & 3;        // warp M index (0..3) -> 32 rows
    const int wn   = wid >> 2;       // warp N index (0..1) -> 64 cols
    const int ntCTA   = blockIdx.x;          // cout tile 0/1
    const int pixBase = blockIdx.y * 128;

    // A-copy ownership: thread -> pixel row (tid>>1), half (tid&1) of 32 k-floats.
    const int rowA  = tid >> 1;
    const int halfA = tid & 1;
    const int pix = pixBase + rowA;
    const int n   = pix / HW;
    const int rm  = pix - n * HW;
    const int oh  = rm / W_;
    const int ow  = rm - oh * W_;
    const int rowSw = rowA & 7;

    float acc[2][8][4];
    #pragma unroll
    for (int mt = 0; mt < 2; ++mt)
        #pragma unroll
        for (int nt = 0; nt < 8; ++nt)
            #pragma unroll
            for (int e = 0; e < 4; ++e) acc[mt][nt][e] = 0.f;

    // -------- issue cp.async copies for slab s into buffer buf --------
    auto issue_copies = [&](int s, int buf) {
        const uint32_t Ab = sb + (uint32_t)buf * 32768u;
        const uint32_t Bb = Ab + 16384u;
        const int f = s >> 2, cs = s & 3;
        const int kh = f / 3, kw = f - kh * 3;
        const int ih = oh + kh - 1, iw = ow + kw - 1;
        const bool inb = (unsigned)ih < (unsigned)H_ && (unsigned)iw < (unsigned)W_;
        const float* srcA = inb
            ? in + (((size_t)(n * H_ + ih) * W_ + iw) << 7) + cs * 32 + halfA * 16
            : in;
        const int sz = inb ? 16 : 0;
        #pragma unroll
        for (int q = 0; q < 4; ++q) {
            const int j = halfA * 4 + q;
            cpasync16(Ab + (uint32_t)(rowA * 128 + ((j ^ rowSw) << 4)), srcA + q * 4, sz);
        }
        const float* srcB = &g_Bp[ntCTA][s][0] + tid * 4;
        #pragma unroll
        for (int q = 0; q < 4; ++q)
            cpasync16(Bb + (uint32_t)(tid * 16 + q * 4096), srcB + q * 1024, 16);
    };

    // prologue: slab 0 into buffer 0
    issue_copies(0, 0);
    asm volatile("cp.async.commit_group;" ::: "memory");
    asm volatile("cp.async.wait_group 0;" ::: "memory");
    __syncthreads();

    #pragma unroll 1
    for (int s = 0; s < NSLAB; ++s) {
        if (s + 1 < NSLAB) {
            issue_copies(s + 1, (s + 1) & 1);
            asm volatile("cp.async.commit_group;" ::: "memory");
        }

        // -------- compute slab s from buffer s&1 --------
        const uint32_t* As = (const uint32_t*)(smem + (size_t)(s & 1) * 32768);
        const uint32_t* Bs = As + 4096;

        #pragma unroll
        for (int ks = 0; ks < 4; ++ks) {
            const int u0 = ((ks * 2) ^ g) * 4 + tig;      // float offset in 32-float row
            const int u1 = ((ks * 2 + 1) ^ g) * 4 + tig;
            uint32_t a[2][4], b[8][2];
            #pragma unroll
            for (int mt = 0; mt < 2; ++mt) {
                const int r0 = (wm * 32 + mt * 16 + g) * 32;
                const int r1 = r0 + 8 * 32;
                a[mt][0] = As[r0 + u0];
                a[mt][1] = As[r1 + u0];
                a[mt][2] = As[r0 + u1];
                a[mt][3] = As[r1 + u1];
            }
            #pragma unroll
            for (int nt = 0; nt < 8; ++nt) {
                const int nb = (wn * 64 + nt * 8 + g) * 32;
                b[nt][0] = Bs[nb + u0];
                b[nt][1] = Bs[nb + u1];
            }
            #pragma unroll
            for (int mt = 0; mt < 2; ++mt)
                #pragma unroll
                for (int nt = 0; nt < 8; ++nt)
                    MMA_TF32(acc[mt][nt], a[mt], b[nt]);
        }

        asm volatile("cp.async.wait_group 0;" ::: "memory");
        __syncthreads();
    }

    // -------- epilogue: bias + ReLU, direct float2 stores --------
    #pragma unroll
    for (int nt = 0; nt < 8; ++nt) {
        const int col = ntCTA * 128 + wn * 64 + nt * 8 + tig * 2;
        const float2 bb = *(const float2*)&bias[col];
        #pragma unroll
        for (int mt = 0; mt < 2; ++mt) {
            const int r0 = pixBase + wm * 32 + mt * 16 + g;
            float2 v0, v1;
            v0.x = fmaxf(acc[mt][nt][0] + bb.x, 0.f);
            v0.y = fmaxf(acc[mt][nt][1] + bb.y, 0.f);
            v1.x = fmaxf(acc[mt][nt][2] + bb.x, 0.f);
            v1.y = fmaxf(acc[mt][nt][3] + bb.y, 0.f);
            *(float2*)&out[(size_t)r0 * COUT + col] = v0;
            *(float2*)&out[(size_t)(r0 + 8) * COUT + col] = v1;
        }
    }
}

extern "C" void kernel_launch(void* const* d_in, const int* in_sizes, int n_in,
                              void* d_out, int out_size) {
    const float* prev_a   = (const float*)d_in[0];   // [32,56,56,128]
    const float* filter_w = (const float*)d_in[1];   // [3,3,128,256]
    const float* filter_b = (const float*)d_in[2];   // [256]
    float* out = (float*)d_out;                      // [100352,256]

    prepack_kernel<<<dim3(NSLAB, 2), 256>>>(filter_w);

    cudaFuncSetAttribute(conv_mma_tf32, cudaFuncAttributeMaxDynamicSharedMemorySize,
                         SMEM_BYTES);
    conv_mma_tf32<<<dim3(2, 784), 256, SMEM_BYTES>>>(prev_a, filter_b, out);
}

// round 5
// speedup vs baseline: 3.6399x; 1.0725x over previous
#include <cuda_runtime.h>
#include <cstdint>
#include <cstddef>

// CustomConv 3x3 s1 p1: NHWC(32,56,56,128) x HWIO(3,3,128,256) + bias + ReLU.
// Implicit GEMM on mma.sync m16n8k8 tf32 (legacy tensor path; tcgen05 PTX is
// rejected because the harness compiles for compute_100, not compute_100a).
//
// Round-5: fixes round-4 layout collision (wn stride 128 -> 512 granules).
//  * B prepacked FRAGMENT-MAJOR: each thread's 16 B-values per ks live in 4
//    contiguous 16B granules (XOR j^tig swizzle) -> 4x LDS.128 instead of
//    16x LDS.32 per ks (per-ks LDS count 24 -> 12).
//  * 3-stage cp.async pipeline (wait_group 1), one barrier per slab.

#define H_ 56
#define W_ 56
#define HW 3136
#define COUT 256
#define NSLAB 36

// Prepacked B, fragment-major; 16KB per (cout-tile, slab).
__device__ float g_Bp[2][NSLAB][4096];

static __device__ __forceinline__ uint32_t smem_u32(const void* p) {
    uint32_t a;
    asm("{ .reg .u64 t; cvta.to.shared.u64 t, %1; cvt.u32.u64 %0, t; }"
        : "=r"(a) : "l"(p));
    return a;
}
static __device__ __forceinline__ float rna_tf32(float x) {
    uint32_t r;
    asm("cvt.rna.tf32.f32 %0, %1;" : "=r"(r) : "f"(x));
    return __uint_as_float(r);
}
static __device__ __forceinline__ void cpasync16(uint32_t dst, const void* src, int sz) {
    asm volatile("cp.async.cg.shared.global [%0], [%1], 16, %2;"
                 :: "r"(dst), "l"(src), "r"(sz) : "memory");
}

#define MMA_TF32(d, a, b)                                                          \
    asm volatile(                                                                  \
        "mma.sync.aligned.m16n8k8.row.col.f32.tf32.tf32.f32 "                      \
        "{%0,%1,%2,%3}, {%4,%5,%6,%7}, {%8,%9}, {%0,%1,%2,%3};"                    \
        : "+f"((d)[0]), "+f"((d)[1]), "+f"((d)[2]), "+f"((d)[3])                   \
        : "r"((a)[0]), "r"((a)[1]), "r"((a)[2]), "r"((a)[3]),                      \
          "r"((b)[0]), "r"((b)[1]))

// ---------------- weight prepack (once per launch, ~1.2MB) ----------------
// Fragment-major layout, granule (16B) index:
//   granule = wn*512 + ks*128 + idx*4 + (j ^ tig),  idx = tig*8 + g
//   element e in granule: value = W[k = ks*8 + tig + (e&1)*4]
//                                 [n = wn*64 + (2*j + (e>>1))*8 + g]
__global__ void prepack_kernel(const float* __restrict__ wgt) {
    const int s  = blockIdx.x;     // slab 0..35
    const int nt = blockIdx.y;     // cout tile 0..1
    const int t  = threadIdx.x;    // 0..255
    const int f  = s >> 2;         // tap 0..8
    const int cs = s & 3;          // cin slab
    float* dst = &g_Bp[nt][s][0];
    #pragma unroll
    for (int q = 0; q < 16; ++q) {
        const int l   = t * 16 + q;
        const int e   = l & 3;
        const int j   = (l >> 2) & 3;
        const int idx = (l >> 4) & 31;
        const int ks  = (l >> 9) & 3;
        const int wn  = l >> 11;
        const int tig = idx >> 3;
        const int g   = idx & 7;
        const int k   = ks * 8 + tig + (e & 1) * 4;
        const int n   = wn * 64 + (2 * j + (e >> 1)) * 8 + g;
        const int o   = (wn * 512 + ks * 128 + idx * 4 + (j ^ tig)) * 4 + e;
        dst[o] = rna_tf32(wgt[(size_t)(f * 128 + cs * 32 + k) * COUT + nt * 128 + n]);
    }
}

// ---------------- main kernel ----------------
// dyn smem: 3 stages x (A 16KB + B 16KB) = 98304 bytes; 2 CTAs/SM (192KB).
#define SMEM_BYTES 98304

__global__ __launch_bounds__(256, 2)
void conv_mma_tf32(const float* __restrict__ in, const float* __restrict__ bias,
                   float* __restrict__ out) {
    extern __shared__ char smem[];
    const uint32_t sb = smem_u32(smem);
    const int tid  = threadIdx.x;
    const int lane = tid & 31;
    const int wid  = tid >> 5;
    const int g    = lane >> 2;      // groupID 0..7
    const int tig  = lane & 3;       // thread-in-group
    const int wm   = wid & 3;        // warp M index -> 32 rows
    const int wn   = wid >> 2;       // warp N index -> 64 cols
    const int ntCTA   = blockIdx.x;
    const int pixBase = blockIdx.y * 128;

    // A-copy ownership: thread -> pixel row (tid>>1), half (tid&1) of 32 k-floats.
    const int rowA  = tid >> 1;
    const int halfA = tid & 1;
    const int pix = pixBase + rowA;
    const int n   = pix / HW;
    const int rm  = pix - n * HW;
    const int oh  = rm / W_;
    const int ow  = rm - oh * W_;
    const int rowSw = rowA & 7;

    float acc[2][8][4];
    #pragma unroll
    for (int mt = 0; mt < 2; ++mt)
        #pragma unroll
        for (int nt = 0; nt < 8; ++nt)
            #pragma unroll
            for (int e = 0; e < 4; ++e) acc[mt][nt][e] = 0.f;

    auto issue_copies = [&](int s, int stage) {
        const uint32_t Ab = sb + (uint32_t)stage * 32768u;
        const uint32_t Bb = Ab + 16384u;
        const int f = s >> 2, cs = s & 3;
        const int kh = f / 3, kw = f - kh * 3;
        const int ih = oh + kh - 1, iw = ow + kw - 1;
        const bool inb = (unsigned)ih < (unsigned)H_ && (unsigned)iw < (unsigned)W_;
        const float* srcA = inb
            ? in + (((size_t)(n * H_ + ih) * W_ + iw) << 7) + cs * 32 + halfA * 16
            : in;
        const int sz = inb ? 16 : 0;
        #pragma unroll
        for (int q = 0; q < 4; ++q) {
            const int j = halfA * 4 + q;
            cpasync16(Ab + (uint32_t)(rowA * 128 + ((j ^ rowSw) << 4)), srcA + q * 4, sz);
        }
        const float* srcB = &g_Bp[ntCTA][s][0] + tid * 4;
        #pragma unroll
        for (int q = 0; q < 4; ++q)
            cpasync16(Bb + (uint32_t)(tid * 16 + q * 4096), srcB + q * 1024, 16);
    };

    // Prologue: slabs 0 and 1 into stages 0 and 1.
    issue_copies(0, 0);
    asm volatile("cp.async.commit_group;" ::: "memory");
    issue_copies(1, 1);
    asm volatile("cp.async.commit_group;" ::: "memory");

    // Per-thread B fragment base (byte offset within a B buffer).
    const uint32_t bfragBase = (uint32_t)((wn * 512 + (tig * 8 + g) * 4) << 4);

    int stage = 0;     // stage of slab s
    #pragma unroll 1
    for (int s = 0; s < NSLAB; ++s) {
        asm volatile("cp.async.wait_group 1;" ::: "memory");
        __syncthreads();

        if (s + 2 < NSLAB) {
            int st2 = stage + 2; if (st2 >= 3) st2 -= 3;
            issue_copies(s + 2, st2);
        }
        asm volatile("cp.async.commit_group;" ::: "memory");

        const char* Abuf = smem + (size_t)stage * 32768;
        const uint32_t* As = (const uint32_t*)Abuf;
        const char* Bbuf = Abuf + 16384;

        #pragma unroll
        for (int ks = 0; ks < 4; ++ks) {
            const int u0 = ((ks * 2) ^ g) * 4 + tig;
            const int u1 = ((ks * 2 + 1) ^ g) * 4 + tig;
            uint32_t a[2][4];
            #pragma unroll
            for (int mt = 0; mt < 2; ++mt) {
                const int r0 = (wm * 32 + mt * 16 + g) * 32;
                const int r1 = r0 + 8 * 32;
                a[mt][0] = As[r0 + u0];
                a[mt][1] = As[r1 + u0];
                a[mt][2] = As[r0 + u1];
                a[mt][3] = As[r1 + u1];
            }
            uint32_t b[8][2];
            #pragma unroll
            for (int j = 0; j < 4; ++j) {
                const uint4 v = *(const uint4*)(Bbuf + bfragBase + ks * 2048
                                                + ((j ^ tig) << 4));
                b[2 * j][0]     = v.x;
                b[2 * j][1]     = v.y;
                b[2 * j + 1][0] = v.z;
                b[2 * j + 1][1] = v.w;
            }
            #pragma unroll
            for (int mt = 0; mt < 2; ++mt)
                #pragma unroll
                for (int nt = 0; nt < 8; ++nt)
                    MMA_TF32(acc[mt][nt], a[mt], b[nt]);
        }

        ++stage; if (stage >= 3) stage = 0;
    }

    // -------- epilogue: bias + ReLU, direct float2 stores --------
    #pragma unroll
    for (int nt = 0; nt < 8; ++nt) {
        const int col = ntCTA * 128 + wn * 64 + nt * 8 + tig * 2;
        const float2 bb = *(const float2*)&bias[col];
        #pragma unroll
        for (int mt = 0; mt < 2; ++mt) {
            const int r0 = pixBase + wm * 32 + mt * 16 + g;
            float2 v0, v1;
            v0.x = fmaxf(acc[mt][nt][0] + bb.x, 0.f);
            v0.y = fmaxf(acc[mt][nt][1] + bb.y, 0.f);
            v1.x = fmaxf(acc[mt][nt][2] + bb.x, 0.f);
            v1.y = fmaxf(acc[mt][nt][3] + bb.y, 0.f);
            *(float2*)&out[(size_t)r0 * COUT + col] = v0;
            *(float2*)&out[(size_t)(r0 + 8) * COUT + col] = v1;
        }
    }
}

extern "C" void kernel_launch(void* const* d_in, const int* in_sizes, int n_in,
                              void* d_out, int out_size) {
    const float* prev_a   = (const float*)d_in[0];   // [32,56,56,128]
    const float* filter_w = (const float*)d_in[1];   // [3,3,128,256]
    const float* filter_b = (const float*)d_in[2];   // [256]
    float* out = (float*)d_out;                      // [100352,256]

    prepack_kernel<<<dim3(NSLAB, 2), 256>>>(filter_w);

    cudaFuncSetAttribute(conv_mma_tf32, cudaFuncAttributeMaxDynamicSharedMemorySize,
                         SMEM_BYTES);
    conv_mma_tf32<<<dim3(2, 784), 256, SMEM_BYTES>>>(prev_a, filter_b, out);
}